// round 15
// baseline (speedup 1.0000x reference)
#include <cuda_runtime.h>
#include <cuda_bf16.h>
#include <cuda_fp16.h>
#include <cstdint>

#define N_NODES 50000
#define N_EDGES 500000
#define D_NODE  128
#define D_EDGE  64
#define D_HID   256
#define D_OUT   64

// P[node][0:256] = nf@W1a + b1 ; P[node][256:512] = nf@W1b
__device__ float g_P[(size_t)N_NODES * 512];
// W1^T bf16 split (panels 0-3 only, used by k_pre), swizzled 128B rows
__device__ __nv_bfloat16 gW1T_h[4 * 256 * 64];
__device__ __nv_bfloat16 gW1T_l[4 * 256 * 64];
// W1c^T fp16 [256 n][64 k] swizzled (edge GEMM1 B)
__device__ __half gW1cF[256 * 64];
// W2^T fp16, 4 k-panels of [64 n][64 k] swizzled (edge GEMM2 B)
__device__ __half gW2F[4 * 64 * 64];
__device__ int g_idx64;

// ---------------- helpers ----------------
__device__ __forceinline__ uint32_t s2u(const void* p) {
    return (uint32_t)__cvta_generic_to_shared(p);
}
__device__ __forceinline__ uint32_t pswz(uint32_t row, uint32_t kbyte) {
    return row * 128u + (kbyte ^ ((row & 7u) << 4));
}
__device__ __forceinline__ void ldm_x4(uint32_t* r, uint32_t addr) {
    asm volatile("ldmatrix.sync.aligned.m8n8.x4.shared.b16 {%0,%1,%2,%3}, [%4];"
        : "=r"(r[0]), "=r"(r[1]), "=r"(r[2]), "=r"(r[3]) : "r"(addr));
}
__device__ __forceinline__ void mma_bf(float* c, const uint32_t* a, const uint32_t* b) {
    asm volatile("mma.sync.aligned.m16n8k16.row.col.f32.bf16.bf16.f32 "
        "{%0,%1,%2,%3}, {%4,%5,%6,%7}, {%8,%9}, {%0,%1,%2,%3};"
        : "+f"(c[0]), "+f"(c[1]), "+f"(c[2]), "+f"(c[3])
        : "r"(a[0]), "r"(a[1]), "r"(a[2]), "r"(a[3]), "r"(b[0]), "r"(b[1]));
}
__device__ __forceinline__ void mma_fp(float* c, const uint32_t* a, const uint32_t* b) {
    asm volatile("mma.sync.aligned.m16n8k16.row.col.f32.f16.f16.f32 "
        "{%0,%1,%2,%3}, {%4,%5,%6,%7}, {%8,%9}, {%0,%1,%2,%3};"
        : "+f"(c[0]), "+f"(c[1]), "+f"(c[2]), "+f"(c[3])
        : "r"(a[0]), "r"(a[1]), "r"(a[2]), "r"(a[3]), "r"(b[0]), "r"(b[1]));
}
// bf16 2-way split (k_pre)
__device__ __forceinline__ void split2(float a, float b, uint32_t& hi, uint32_t& lo) {
    __nv_bfloat16 ha = __float2bfloat16_rn(a), hb = __float2bfloat16_rn(b);
    float la = a - __bfloat162float(ha), lb = b - __bfloat162float(hb);
    __nv_bfloat162 th; th.x = ha; th.y = hb;
    __nv_bfloat162 tl; tl.x = __float2bfloat16_rn(la); tl.y = __float2bfloat16_rn(lb);
    hi = *reinterpret_cast<uint32_t*>(&th);
    lo = *reinterpret_cast<uint32_t*>(&tl);
}
// fp16 pack (k_edge activations, single-term)
__device__ __forceinline__ uint32_t packh(float a, float b) {
    __half2 t = __halves2half2(__float2half_rn(a), __float2half_rn(b));
    return *reinterpret_cast<uint32_t*>(&t);
}

// ---------------- dtype detect ----------------
__global__ void k_detect(const int* __restrict__ EIw) {
    if (threadIdx.x == 0 && blockIdx.x == 0) {
        int allzero = 1;
        #pragma unroll 1
        for (int i = 0; i < 64; i++)
            if (EIw[2 * i + 1] != 0) { allzero = 0; break; }
        g_idx64 = allzero;
    }
}

// ---------------- weight conversion ----------------
__global__ __launch_bounds__(256) void k_convw(
    const float* __restrict__ W1, const float* __restrict__ W2)
{
    int idx = blockIdx.x * 256 + threadIdx.x;
    if (idx < 4 * 256 * 64) {
        int p = idx / 16384, r = idx % 16384;
        int n = r / 64, kl = r % 64;
        float v = W1[(size_t)(p * 64 + kl) * D_HID + n];
        __nv_bfloat16 h = __float2bfloat16_rn(v);
        float lo = v - __bfloat162float(h);
        uint32_t off = (uint32_t)p * 32768u + pswz(n, 2 * kl);
        *(__nv_bfloat16*)((char*)gW1T_h + off) = h;
        *(__nv_bfloat16*)((char*)gW1T_l + off) = __float2bfloat16_rn(lo);
    } else if (idx < 4 * 256 * 64 + 16384) {
        int j = idx - 4 * 256 * 64;
        int n = j / 64, kl = j % 64;
        float v = W1[(size_t)(256 + kl) * D_HID + n];
        *(__half*)((char*)gW1cF + pswz(n, 2 * kl)) = __float2half_rn(v);
    } else if (idx < 4 * 256 * 64 + 32768) {
        int j = idx - 4 * 256 * 64 - 16384;
        int p = j / 4096, r = j % 4096;
        int n = r / 64, kl = r % 64;
        float v = W2[(size_t)(p * 64 + kl) * D_OUT + n];
        *(__half*)((char*)gW2F + (uint32_t)p * 8192u + pswz(n, 2 * kl)) = __float2half_rn(v);
    }
}

// ---------------- kernel 1: P table via bf16-split MMA (unchanged) --------
__global__ __launch_bounds__(256) void k_pre(
    const float* __restrict__ NF, const float* __restrict__ b1)
{
    extern __shared__ char sm[];
    const uint32_t uA_h = s2u(sm), uA_l = uA_h + 32768;
    const uint32_t uB_h = uA_h + 65536, uB_l = uA_h + 98304;

    const int tid = threadIdx.x, lane = tid & 31, wid = tid >> 5;
    const int wm = wid & 3, wn = wid >> 2;
    const int m0 = blockIdx.x * 128;

    const uint32_t a_row = (lane & 7) + ((lane >> 3) & 1) * 8;
    const uint32_t a_kb  = (lane >> 4) * 16;
    const uint32_t b_row = (lane & 7) + (lane >> 4) * 8;
    const uint32_t b_kb  = ((lane >> 3) & 1) * 16;

    #pragma unroll
    for (int t = 0; t < 32; t++) {
        int idx = tid + t * 256;
        int e = idx >> 6, kp = idx & 63;
        int gm = m0 + e;
        float2 v = make_float2(0.f, 0.f);
        if (gm < N_NODES) v = *(const float2*)(NF + (size_t)gm * D_NODE + 2 * kp);
        uint32_t hi, lo; split2(v.x, v.y, hi, lo);
        uint32_t off = (uint32_t)(kp >> 5) * 16384u + pswz(e, (kp & 31) * 4);
        *(uint32_t*)(sm + off) = hi;
        *(uint32_t*)(sm + 32768 + off) = lo;
    }
    __syncthreads();

    for (int c = 0; c < 4; c++) {
        const int p0 = (c < 2) ? 0 : 2;
        const int wc0 = (c & 1) * 128;
        const uint32_t* srcH = (const uint32_t*)(gW1T_h);
        const uint32_t* srcL = (const uint32_t*)(gW1T_l);
        #pragma unroll
        for (int d = 0; d < 2; d++) {
            size_t so = ((size_t)(p0 + d) * 16384 + (size_t)wc0 * 64) / 2;
            #pragma unroll
            for (int t = 0; t < 16; t++) {
                int w = tid + t * 256;
                ((uint32_t*)(sm + 65536 + d * 16384))[w] = srcH[so + w];
                ((uint32_t*)(sm + 98304 + d * 16384))[w] = srcL[so + w];
            }
        }
        __syncthreads();

        float acc[2][8][4];
        #pragma unroll
        for (int i = 0; i < 2; i++)
            #pragma unroll
            for (int j = 0; j < 8; j++)
                #pragma unroll
                for (int r = 0; r < 4; r++) acc[i][j][r] = 0.f;

        #pragma unroll
        for (int ks = 0; ks < 8; ks++) {
            const uint32_t pan = (uint32_t)(ks >> 2) * 16384u;
            const uint32_t kb = (ks & 3) * 32;
            uint32_t Ah[2][4], Al[2][4], Bh[4][4], Bl[4][4];
            #pragma unroll
            for (int mt = 0; mt < 2; mt++) {
                uint32_t row = wm * 32 + mt * 16 + a_row;
                uint32_t off = pan + pswz(row, kb + a_kb);
                ldm_x4(Ah[mt], uA_h + off);
                ldm_x4(Al[mt], uA_l + off);
            }
            #pragma unroll
            for (int np = 0; np < 4; np++) {
                uint32_t row = wn * 64 + np * 16 + b_row;
                uint32_t off = pan + pswz(row, kb + b_kb);
                ldm_x4(Bh[np], uB_h + off);
                ldm_x4(Bl[np], uB_l + off);
            }
            #pragma unroll
            for (int mt = 0; mt < 2; mt++)
                #pragma unroll
                for (int nt = 0; nt < 8; nt++) {
                    const uint32_t* bh = &Bh[nt >> 1][(nt & 1) * 2];
                    const uint32_t* bl = &Bl[nt >> 1][(nt & 1) * 2];
                    mma_bf(acc[mt][nt], Ah[mt], bh);
                    mma_bf(acc[mt][nt], Ah[mt], bl);
                    mma_bf(acc[mt][nt], Al[mt], bh);
                }
        }

        const int g = lane >> 2, tg2 = (lane & 3) * 2;
        #pragma unroll
        for (int mt = 0; mt < 2; mt++) {
            #pragma unroll
            for (int rr = 0; rr < 2; rr++) {
                int gm = m0 + wm * 32 + mt * 16 + g + rr * 8;
                if (gm < N_NODES) {
                    #pragma unroll
                    for (int nt = 0; nt < 8; nt++) {
                        int col = c * 128 + wn * 64 + nt * 8 + tg2;
                        float2 o;
                        o.x = acc[mt][nt][rr * 2 + 0];
                        o.y = acc[mt][nt][rr * 2 + 1];
                        if (c < 2) { o.x += b1[col]; o.y += b1[col + 1]; }
                        *(float2*)(g_P + (size_t)gm * 512 + col) = o;
                    }
                }
            }
        }
        __syncthreads();
    }
}

// ---------------- kernel 2: pure-fp16 register-chained edge MLP -----------
// 64 edges/CTA, 256 threads (8 warps: wm4 x wn2), 72KB smem, target 3 CTA/SM.
// Single-term fp16 activations AND weights: 1 MMA per B fragment.
__global__ __launch_bounds__(256, 3) void k_edge(
    const int* __restrict__ EIw, const float* __restrict__ EA,
    const float* __restrict__ b2, float* __restrict__ out)
{
    extern __shared__ char sm[];
    const uint32_t uBase = s2u(sm);
    const uint32_t uEA = uBase;                  // 8KB fp16 EA (hi only)
    const uint32_t uW1 = uBase + 8192;           // 32KB fp16 W1c
    const uint32_t uW2 = uBase + 40960;          // 32KB fp16 W2
    float* red = (float*)sm;   // overlays EA/W1c after final sync

    __shared__ int sRow[64], sCol[64];

    const int tid = threadIdx.x, lane = tid & 31, wid = tid >> 5;
    const int wm = wid >> 1, wn = wid & 1;   // 4 x 2 warp grid
    const int e0 = blockIdx.x * 64;
    const int g = lane >> 2, tg2 = (lane & 3) * 2;

    const uint32_t a_row = (lane & 7) + ((lane >> 3) & 1) * 8;
    const uint32_t a_kb  = (lane >> 4) * 16;
    const uint32_t b_row = (lane & 7) + (lane >> 4) * 8;
    const uint32_t b_kb  = ((lane >> 3) & 1) * 16;

    if (tid < 64) {
        int e = e0 + tid;
        int r = 0, c = 0;
        if (e < N_EDGES) {
            if (g_idx64) { r = EIw[(size_t)2 * e]; c = EIw[(size_t)2 * (N_EDGES + e)]; }
            else         { r = EIw[e];             c = EIw[(size_t)N_EDGES + e]; }
        }
        sRow[tid] = min(max(r, 0), N_NODES - 1);
        sCol[tid] = min(max(c, 0), N_NODES - 1);
    }
    // EA tile [64e][64k] -> single fp16 panel
    #pragma unroll
    for (int t = 0; t < 8; t++) {
        int idx = tid + t * 256;
        int e = idx >> 5, kp = idx & 31;
        int ge = e0 + e;
        float2 v = make_float2(0.f, 0.f);
        if (ge < N_EDGES) v = *(const float2*)(EA + (size_t)ge * D_EDGE + 2 * kp);
        *(uint32_t*)(sm + pswz(e, kp * 4)) = packh(v.x, v.y);
    }
    // W1c fp16 [256n][64k]: 8192 words
    #pragma unroll
    for (int t = 0; t < 32; t++) {
        int w = tid + t * 256;
        ((uint32_t*)(sm + 8192))[w] = ((const uint32_t*)gW1cF)[w];
    }
    // W2 fp16 4 k-panels: 8192 words
    #pragma unroll
    for (int t = 0; t < 32; t++) {
        int w = tid + t * 256;
        ((uint32_t*)(sm + 40960))[w] = ((const uint32_t*)gW2F)[w];
    }
    __syncthreads();   // the ONLY barrier before the output reduction

    float d[8][4];
    #pragma unroll
    for (int j = 0; j < 8; j++)
        #pragma unroll
        for (int r = 0; r < 4; r++) d[j][r] = 0.f;

    const int eg = wm * 16 + g;

    #pragma unroll 1
    for (int h = 0; h < 2; h++) {
        // ---- GEMM1: acc[16e x 64hid], hid slice = h*128 + wn*64 ----
        float acc[8][4];
        #pragma unroll
        for (int j = 0; j < 8; j++)
            #pragma unroll
            for (int r = 0; r < 4; r++) acc[j][r] = 0.f;

        #pragma unroll
        for (int ks = 0; ks < 4; ks++) {
            const uint32_t kb = ks * 32;
            uint32_t Ah[4];
            ldm_x4(Ah, uEA + pswz(wm * 16 + a_row, kb + a_kb));
            #pragma unroll
            for (int np = 0; np < 4; np++) {
                uint32_t B4[4];
                uint32_t row = h * 128 + wn * 64 + np * 16 + b_row;
                ldm_x4(B4, uW1 + pswz(row, kb + b_kb));
                #pragma unroll
                for (int pr = 0; pr < 2; pr++)
                    mma_fp(acc[np * 2 + pr], Ah, &B4[pr * 2]);
            }
        }

        // ---- epilogue (gather P, relu, fp16 pack) + GEMM2 partial ----
        const int pc = h * 128 + wn * 64;
        const float* paG  = g_P + (size_t)sRow[eg]     * 512 + pc;
        const float* paG8 = g_P + (size_t)sRow[eg + 8] * 512 + pc;
        const float* pbG  = g_P + (size_t)sCol[eg]     * 512 + 256 + pc;
        const float* pbG8 = g_P + (size_t)sCol[eg + 8] * 512 + 256 + pc;
        const uint32_t w2 = uW2 + (uint32_t)(2 * h + wn) * 8192u;

        #pragma unroll
        for (int j = 0; j < 4; j++) {
            const int c0 = j * 16 + tg2, c1 = c0 + 8;
            float2 va0 = __ldg((const float2*)(paG  + c0));
            float2 vb0 = __ldg((const float2*)(pbG  + c0));
            float2 wa0 = __ldg((const float2*)(paG8 + c0));
            float2 wb0 = __ldg((const float2*)(pbG8 + c0));
            float2 va1 = __ldg((const float2*)(paG  + c1));
            float2 vb1 = __ldg((const float2*)(pbG  + c1));
            float2 wa1 = __ldg((const float2*)(paG8 + c1));
            float2 wb1 = __ldg((const float2*)(pbG8 + c1));

            float x00 = fmaxf(acc[2*j][0]   + va0.x + vb0.x, 0.f);
            float x01 = fmaxf(acc[2*j][1]   + va0.y + vb0.y, 0.f);
            float x10 = fmaxf(acc[2*j][2]   + wa0.x + wb0.x, 0.f);
            float x11 = fmaxf(acc[2*j][3]   + wa0.y + wb0.y, 0.f);
            float y00 = fmaxf(acc[2*j+1][0] + va1.x + vb1.x, 0.f);
            float y01 = fmaxf(acc[2*j+1][1] + va1.y + vb1.y, 0.f);
            float y10 = fmaxf(acc[2*j+1][2] + wa1.x + wb1.x, 0.f);
            float y11 = fmaxf(acc[2*j+1][3] + wa1.y + wb1.y, 0.f);

            // C-tile pair -> A-fragment (m16k16), single fp16
            uint32_t aH[4];
            aH[0] = packh(x00, x01);
            aH[1] = packh(x10, x11);
            aH[2] = packh(y00, y01);
            aH[3] = packh(y10, y11);

            #pragma unroll
            for (int np = 0; np < 4; np++) {
                uint32_t B4[4];
                ldm_x4(B4, w2 + pswz(np * 16 + b_row, j * 32 + b_kb));
                #pragma unroll
                for (int pr = 0; pr < 2; pr++)
                    mma_fp(d[np * 2 + pr], aH, &B4[pr * 2]);
            }
        }
    }

    // ---- cross-wn reduction (stride-68 buffer overlaying EA/W1c) ----
    __syncthreads();
    if (wn == 1) {
        #pragma unroll
        for (int nt = 0; nt < 8; nt++) {
            int n = nt * 8 + tg2;
            int el = wm * 16 + g;
            *(float2*)(red + (size_t)el * 68 + n) =
                make_float2(d[nt][0], d[nt][1]);
            *(float2*)(red + (size_t)(el + 8) * 68 + n) =
                make_float2(d[nt][2], d[nt][3]);
        }
    }
    __syncthreads();
    if (wn == 0) {
        #pragma unroll
        for (int rr = 0; rr < 2; rr++) {
            int el = wm * 16 + g + rr * 8;
            int ge = e0 + el;
            if (ge < N_EDGES) {
                #pragma unroll
                for (int nt = 0; nt < 8; nt++) {
                    int n = nt * 8 + tg2;
                    float2 r2 = *(float2*)(red + (size_t)el * 68 + n);
                    float2 bb = *(const float2*)(b2 + n);
                    float2 o;
                    o.x = d[nt][rr * 2 + 0] + r2.x + bb.x;
                    o.y = d[nt][rr * 2 + 1] + r2.y + bb.y;
                    *(float2*)(out + (size_t)ge * D_OUT + n) = o;
                }
            }
        }
    }
}

// ---------------------------------------------------------------------------
extern "C" void kernel_launch(void* const* d_in, const int* in_sizes, int n_in,
                              void* d_out, int out_size) {
    const float* NF  = (const float*)d_in[0];
    const int*   EIw = (const int*)d_in[1];
    const float* EA  = (const float*)d_in[2];
    const float* W1  = (const float*)d_in[3];
    const float* b1  = (const float*)d_in[4];
    const float* W2  = (const float*)d_in[5];
    const float* b2  = (const float*)d_in[6];
    float* out = (float*)d_out;

    static int attr_set = 0;
    if (!attr_set) {
        cudaFuncSetAttribute(k_pre, cudaFuncAttributeMaxDynamicSharedMemorySize, 131072);
        cudaFuncSetAttribute(k_edge, cudaFuncAttributeMaxDynamicSharedMemorySize, 73728);
        attr_set = 1;
    }

    k_detect<<<1, 32>>>(EIw);
    k_convw<<<(4 * 256 * 64 + 32768 + 255) / 256, 256>>>(W1, W2);
    k_pre<<<(N_NODES + 127) / 128, 256, 131072>>>(NF, b1);
    k_edge<<<(N_EDGES + 63) / 64, 256, 73728>>>(EIw, EA, b2, out);
}

// round 16
// speedup vs baseline: 1.5789x; 1.5789x over previous
#include <cuda_runtime.h>
#include <cuda_bf16.h>
#include <cuda_fp16.h>
#include <cstdint>

#define N_NODES 50000
#define N_EDGES 500000
#define D_NODE  128
#define D_EDGE  64
#define D_HID   256
#define D_OUT   64

// P[node][0:256] = nf@W1a + b1 ; P[node][256:512] = nf@W1b
__device__ float g_P[(size_t)N_NODES * 512];
// W1^T bf16 split (panels 0-3 only, used by k_pre), swizzled 128B rows
__device__ __nv_bfloat16 gW1T_h[4 * 256 * 64];
__device__ __nv_bfloat16 gW1T_l[4 * 256 * 64];
// W1c^T fp16 [256 n][64 k] swizzled (edge GEMM1 B)
__device__ __half gW1cF[256 * 64];
// W2^T fp16, 4 k-panels of [64 n][64 k] swizzled (edge GEMM2 B)
__device__ __half gW2F[4 * 64 * 64];
__device__ int g_idx64;

// ---------------- helpers ----------------
__device__ __forceinline__ uint32_t s2u(const void* p) {
    return (uint32_t)__cvta_generic_to_shared(p);
}
__device__ __forceinline__ uint32_t pswz(uint32_t row, uint32_t kbyte) {
    return row * 128u + (kbyte ^ ((row & 7u) << 4));
}
__device__ __forceinline__ void ldm_x4(uint32_t* r, uint32_t addr) {
    asm volatile("ldmatrix.sync.aligned.m8n8.x4.shared.b16 {%0,%1,%2,%3}, [%4];"
        : "=r"(r[0]), "=r"(r[1]), "=r"(r[2]), "=r"(r[3]) : "r"(addr));
}
__device__ __forceinline__ void mma_bf(float* c, const uint32_t* a, const uint32_t* b) {
    asm volatile("mma.sync.aligned.m16n8k16.row.col.f32.bf16.bf16.f32 "
        "{%0,%1,%2,%3}, {%4,%5,%6,%7}, {%8,%9}, {%0,%1,%2,%3};"
        : "+f"(c[0]), "+f"(c[1]), "+f"(c[2]), "+f"(c[3])
        : "r"(a[0]), "r"(a[1]), "r"(a[2]), "r"(a[3]), "r"(b[0]), "r"(b[1]));
}
__device__ __forceinline__ void mma_fp(float* c, const uint32_t* a, const uint32_t* b) {
    asm volatile("mma.sync.aligned.m16n8k16.row.col.f32.f16.f16.f32 "
        "{%0,%1,%2,%3}, {%4,%5,%6,%7}, {%8,%9}, {%0,%1,%2,%3};"
        : "+f"(c[0]), "+f"(c[1]), "+f"(c[2]), "+f"(c[3])
        : "r"(a[0]), "r"(a[1]), "r"(a[2]), "r"(a[3]), "r"(b[0]), "r"(b[1]));
}
// bf16 2-way split (k_pre)
__device__ __forceinline__ void split2(float a, float b, uint32_t& hi, uint32_t& lo) {
    __nv_bfloat16 ha = __float2bfloat16_rn(a), hb = __float2bfloat16_rn(b);
    float la = a - __bfloat162float(ha), lb = b - __bfloat162float(hb);
    __nv_bfloat162 th; th.x = ha; th.y = hb;
    __nv_bfloat162 tl; tl.x = __float2bfloat16_rn(la); tl.y = __float2bfloat16_rn(lb);
    hi = *reinterpret_cast<uint32_t*>(&th);
    lo = *reinterpret_cast<uint32_t*>(&tl);
}
// fp16 pack (k_edge activations, single-term)
__device__ __forceinline__ uint32_t packh(float a, float b) {
    __half2 t = __halves2half2(__float2half_rn(a), __float2half_rn(b));
    return *reinterpret_cast<uint32_t*>(&t);
}

// ---------------- dtype detect ----------------
__global__ void k_detect(const int* __restrict__ EIw) {
    if (threadIdx.x == 0 && blockIdx.x == 0) {
        int allzero = 1;
        #pragma unroll 1
        for (int i = 0; i < 64; i++)
            if (EIw[2 * i + 1] != 0) { allzero = 0; break; }
        g_idx64 = allzero;
    }
}

// ---------------- weight conversion ----------------
__global__ __launch_bounds__(256) void k_convw(
    const float* __restrict__ W1, const float* __restrict__ W2)
{
    int idx = blockIdx.x * 256 + threadIdx.x;
    if (idx < 4 * 256 * 64) {
        int p = idx / 16384, r = idx % 16384;
        int n = r / 64, kl = r % 64;
        float v = W1[(size_t)(p * 64 + kl) * D_HID + n];
        __nv_bfloat16 h = __float2bfloat16_rn(v);
        float lo = v - __bfloat162float(h);
        uint32_t off = (uint32_t)p * 32768u + pswz(n, 2 * kl);
        *(__nv_bfloat16*)((char*)gW1T_h + off) = h;
        *(__nv_bfloat16*)((char*)gW1T_l + off) = __float2bfloat16_rn(lo);
    } else if (idx < 4 * 256 * 64 + 16384) {
        int j = idx - 4 * 256 * 64;
        int n = j / 64, kl = j % 64;
        float v = W1[(size_t)(256 + kl) * D_HID + n];
        *(__half*)((char*)gW1cF + pswz(n, 2 * kl)) = __float2half_rn(v);
    } else if (idx < 4 * 256 * 64 + 32768) {
        int j = idx - 4 * 256 * 64 - 16384;
        int p = j / 4096, r = j % 4096;
        int n = r / 64, kl = r % 64;
        float v = W2[(size_t)(p * 64 + kl) * D_OUT + n];
        *(__half*)((char*)gW2F + (uint32_t)p * 8192u + pswz(n, 2 * kl)) = __float2half_rn(v);
    }
}

// ---------------- kernel 1: P table via bf16-split MMA (unchanged) --------
__global__ __launch_bounds__(256) void k_pre(
    const float* __restrict__ NF, const float* __restrict__ b1)
{
    extern __shared__ char sm[];
    const uint32_t uA_h = s2u(sm), uA_l = uA_h + 32768;
    const uint32_t uB_h = uA_h + 65536, uB_l = uA_h + 98304;

    const int tid = threadIdx.x, lane = tid & 31, wid = tid >> 5;
    const int wm = wid & 3, wn = wid >> 2;
    const int m0 = blockIdx.x * 128;

    const uint32_t a_row = (lane & 7) + ((lane >> 3) & 1) * 8;
    const uint32_t a_kb  = (lane >> 4) * 16;
    const uint32_t b_row = (lane & 7) + (lane >> 4) * 8;
    const uint32_t b_kb  = ((lane >> 3) & 1) * 16;

    #pragma unroll
    for (int t = 0; t < 32; t++) {
        int idx = tid + t * 256;
        int e = idx >> 6, kp = idx & 63;
        int gm = m0 + e;
        float2 v = make_float2(0.f, 0.f);
        if (gm < N_NODES) v = *(const float2*)(NF + (size_t)gm * D_NODE + 2 * kp);
        uint32_t hi, lo; split2(v.x, v.y, hi, lo);
        uint32_t off = (uint32_t)(kp >> 5) * 16384u + pswz(e, (kp & 31) * 4);
        *(uint32_t*)(sm + off) = hi;
        *(uint32_t*)(sm + 32768 + off) = lo;
    }
    __syncthreads();

    for (int c = 0; c < 4; c++) {
        const int p0 = (c < 2) ? 0 : 2;
        const int wc0 = (c & 1) * 128;
        const uint32_t* srcH = (const uint32_t*)(gW1T_h);
        const uint32_t* srcL = (const uint32_t*)(gW1T_l);
        #pragma unroll
        for (int d = 0; d < 2; d++) {
            size_t so = ((size_t)(p0 + d) * 16384 + (size_t)wc0 * 64) / 2;
            #pragma unroll
            for (int t = 0; t < 16; t++) {
                int w = tid + t * 256;
                ((uint32_t*)(sm + 65536 + d * 16384))[w] = srcH[so + w];
                ((uint32_t*)(sm + 98304 + d * 16384))[w] = srcL[so + w];
            }
        }
        __syncthreads();

        float acc[2][8][4];
        #pragma unroll
        for (int i = 0; i < 2; i++)
            #pragma unroll
            for (int j = 0; j < 8; j++)
                #pragma unroll
                for (int r = 0; r < 4; r++) acc[i][j][r] = 0.f;

        #pragma unroll
        for (int ks = 0; ks < 8; ks++) {
            const uint32_t pan = (uint32_t)(ks >> 2) * 16384u;
            const uint32_t kb = (ks & 3) * 32;
            uint32_t Ah[2][4], Al[2][4], Bh[4][4], Bl[4][4];
            #pragma unroll
            for (int mt = 0; mt < 2; mt++) {
                uint32_t row = wm * 32 + mt * 16 + a_row;
                uint32_t off = pan + pswz(row, kb + a_kb);
                ldm_x4(Ah[mt], uA_h + off);
                ldm_x4(Al[mt], uA_l + off);
            }
            #pragma unroll
            for (int np = 0; np < 4; np++) {
                uint32_t row = wn * 64 + np * 16 + b_row;
                uint32_t off = pan + pswz(row, kb + b_kb);
                ldm_x4(Bh[np], uB_h + off);
                ldm_x4(Bl[np], uB_l + off);
            }
            #pragma unroll
            for (int mt = 0; mt < 2; mt++)
                #pragma unroll
                for (int nt = 0; nt < 8; nt++) {
                    const uint32_t* bh = &Bh[nt >> 1][(nt & 1) * 2];
                    const uint32_t* bl = &Bl[nt >> 1][(nt & 1) * 2];
                    mma_bf(acc[mt][nt], Ah[mt], bh);
                    mma_bf(acc[mt][nt], Ah[mt], bl);
                    mma_bf(acc[mt][nt], Al[mt], bh);
                }
        }

        const int g = lane >> 2, tg2 = (lane & 3) * 2;
        #pragma unroll
        for (int mt = 0; mt < 2; mt++) {
            #pragma unroll
            for (int rr = 0; rr < 2; rr++) {
                int gm = m0 + wm * 32 + mt * 16 + g + rr * 8;
                if (gm < N_NODES) {
                    #pragma unroll
                    for (int nt = 0; nt < 8; nt++) {
                        int col = c * 128 + wn * 64 + nt * 8 + tg2;
                        float2 o;
                        o.x = acc[mt][nt][rr * 2 + 0];
                        o.y = acc[mt][nt][rr * 2 + 1];
                        if (c < 2) { o.x += b1[col]; o.y += b1[col + 1]; }
                        *(float2*)(g_P + (size_t)gm * 512 + col) = o;
                    }
                }
            }
        }
        __syncthreads();
    }
}

// ---------------- kernel 2: pure-fp16 register-chained edge MLP -----------
// 64 edges/CTA, 256 threads (8 warps: wm4 x wn2), 72KB smem, 2 CTAs/SM.
// Single-term fp16 activations AND weights: 1 MMA per B fragment.
// launch_bounds (256,2): 128-reg budget -> no spills (R15's (256,3) spilled).
__global__ __launch_bounds__(256, 2) void k_edge(
    const int* __restrict__ EIw, const float* __restrict__ EA,
    const float* __restrict__ b2, float* __restrict__ out)
{
    extern __shared__ char sm[];
    const uint32_t uBase = s2u(sm);
    const uint32_t uEA = uBase;                  // 8KB fp16 EA
    const uint32_t uW1 = uBase + 8192;           // 32KB fp16 W1c
    const uint32_t uW2 = uBase + 40960;          // 32KB fp16 W2
    float* red = (float*)sm;   // overlays EA/W1c after final sync

    __shared__ int sRow[64], sCol[64];

    const int tid = threadIdx.x, lane = tid & 31, wid = tid >> 5;
    const int wm = wid >> 1, wn = wid & 1;   // 4 x 2 warp grid
    const int e0 = blockIdx.x * 64;
    const int g = lane >> 2, tg2 = (lane & 3) * 2;

    const uint32_t a_row = (lane & 7) + ((lane >> 3) & 1) * 8;
    const uint32_t a_kb  = (lane >> 4) * 16;
    const uint32_t b_row = (lane & 7) + (lane >> 4) * 8;
    const uint32_t b_kb  = ((lane >> 3) & 1) * 16;

    if (tid < 64) {
        int e = e0 + tid;
        int r = 0, c = 0;
        if (e < N_EDGES) {
            if (g_idx64) { r = EIw[(size_t)2 * e]; c = EIw[(size_t)2 * (N_EDGES + e)]; }
            else         { r = EIw[e];             c = EIw[(size_t)N_EDGES + e]; }
        }
        sRow[tid] = min(max(r, 0), N_NODES - 1);
        sCol[tid] = min(max(c, 0), N_NODES - 1);
    }
    // EA tile [64e][64k] -> single fp16 panel
    #pragma unroll
    for (int t = 0; t < 8; t++) {
        int idx = tid + t * 256;
        int e = idx >> 5, kp = idx & 31;
        int ge = e0 + e;
        float2 v = make_float2(0.f, 0.f);
        if (ge < N_EDGES) v = *(const float2*)(EA + (size_t)ge * D_EDGE + 2 * kp);
        *(uint32_t*)(sm + pswz(e, kp * 4)) = packh(v.x, v.y);
    }
    // W1c fp16 [256n][64k]: 8192 words
    #pragma unroll
    for (int t = 0; t < 32; t++) {
        int w = tid + t * 256;
        ((uint32_t*)(sm + 8192))[w] = ((const uint32_t*)gW1cF)[w];
    }
    // W2 fp16 4 k-panels: 8192 words
    #pragma unroll
    for (int t = 0; t < 32; t++) {
        int w = tid + t * 256;
        ((uint32_t*)(sm + 40960))[w] = ((const uint32_t*)gW2F)[w];
    }
    __syncthreads();   // the ONLY barrier before the output reduction

    float d[8][4];
    #pragma unroll
    for (int j = 0; j < 8; j++)
        #pragma unroll
        for (int r = 0; r < 4; r++) d[j][r] = 0.f;

    const int eg = wm * 16 + g;

    #pragma unroll 1
    for (int h = 0; h < 2; h++) {
        // ---- GEMM1: acc[16e x 64hid], hid slice = h*128 + wn*64 ----
        float acc[8][4];
        #pragma unroll
        for (int j = 0; j < 8; j++)
            #pragma unroll
            for (int r = 0; r < 4; r++) acc[j][r] = 0.f;

        #pragma unroll
        for (int ks = 0; ks < 4; ks++) {
            const uint32_t kb = ks * 32;
            uint32_t Ah[4];
            ldm_x4(Ah, uEA + pswz(wm * 16 + a_row, kb + a_kb));
            #pragma unroll
            for (int np = 0; np < 4; np++) {
                uint32_t B4[4];
                uint32_t row = h * 128 + wn * 64 + np * 16 + b_row;
                ldm_x4(B4, uW1 + pswz(row, kb + b_kb));
                #pragma unroll
                for (int pr = 0; pr < 2; pr++)
                    mma_fp(acc[np * 2 + pr], Ah, &B4[pr * 2]);
            }
        }

        // ---- epilogue (gather P, relu, fp16 pack) + GEMM2 partial ----
        const int pc = h * 128 + wn * 64;
        const float* paG  = g_P + (size_t)sRow[eg]     * 512 + pc;
        const float* paG8 = g_P + (size_t)sRow[eg + 8] * 512 + pc;
        const float* pbG  = g_P + (size_t)sCol[eg]     * 512 + 256 + pc;
        const float* pbG8 = g_P + (size_t)sCol[eg + 8] * 512 + 256 + pc;
        const uint32_t w2 = uW2 + (uint32_t)(2 * h + wn) * 8192u;

        #pragma unroll
        for (int j = 0; j < 4; j++) {
            const int c0 = j * 16 + tg2, c1 = c0 + 8;
            float2 va0 = __ldg((const float2*)(paG  + c0));
            float2 vb0 = __ldg((const float2*)(pbG  + c0));
            float2 wa0 = __ldg((const float2*)(paG8 + c0));
            float2 wb0 = __ldg((const float2*)(pbG8 + c0));
            float2 va1 = __ldg((const float2*)(paG  + c1));
            float2 vb1 = __ldg((const float2*)(pbG  + c1));
            float2 wa1 = __ldg((const float2*)(paG8 + c1));
            float2 wb1 = __ldg((const float2*)(pbG8 + c1));

            float x00 = fmaxf(acc[2*j][0]   + va0.x + vb0.x, 0.f);
            float x01 = fmaxf(acc[2*j][1]   + va0.y + vb0.y, 0.f);
            float x10 = fmaxf(acc[2*j][2]   + wa0.x + wb0.x, 0.f);
            float x11 = fmaxf(acc[2*j][3]   + wa0.y + wb0.y, 0.f);
            float y00 = fmaxf(acc[2*j+1][0] + va1.x + vb1.x, 0.f);
            float y01 = fmaxf(acc[2*j+1][1] + va1.y + vb1.y, 0.f);
            float y10 = fmaxf(acc[2*j+1][2] + wa1.x + wb1.x, 0.f);
            float y11 = fmaxf(acc[2*j+1][3] + wa1.y + wb1.y, 0.f);

            // C-tile pair -> A-fragment (m16k16), single fp16
            uint32_t aH[4];
            aH[0] = packh(x00, x01);
            aH[1] = packh(x10, x11);
            aH[2] = packh(y00, y01);
            aH[3] = packh(y10, y11);

            #pragma unroll
            for (int np = 0; np < 4; np++) {
                uint32_t B4[4];
                ldm_x4(B4, w2 + pswz(np * 16 + b_row, j * 32 + b_kb));
                #pragma unroll
                for (int pr = 0; pr < 2; pr++)
                    mma_fp(d[np * 2 + pr], aH, &B4[pr * 2]);
            }
        }
    }

    // ---- cross-wn reduction (stride-68 buffer overlaying EA/W1c) ----
    __syncthreads();
    if (wn == 1) {
        #pragma unroll
        for (int nt = 0; nt < 8; nt++) {
            int n = nt * 8 + tg2;
            int el = wm * 16 + g;
            *(float2*)(red + (size_t)el * 68 + n) =
                make_float2(d[nt][0], d[nt][1]);
            *(float2*)(red + (size_t)(el + 8) * 68 + n) =
                make_float2(d[nt][2], d[nt][3]);
        }
    }
    __syncthreads();
    if (wn == 0) {
        #pragma unroll
        for (int rr = 0; rr < 2; rr++) {
            int el = wm * 16 + g + rr * 8;
            int ge = e0 + el;
            if (ge < N_EDGES) {
                #pragma unroll
                for (int nt = 0; nt < 8; nt++) {
                    int n = nt * 8 + tg2;
                    float2 r2 = *(float2*)(red + (size_t)el * 68 + n);
                    float2 bb = *(const float2*)(b2 + n);
                    float2 o;
                    o.x = d[nt][rr * 2 + 0] + r2.x + bb.x;
                    o.y = d[nt][rr * 2 + 1] + r2.y + bb.y;
                    *(float2*)(out + (size_t)ge * D_OUT + n) = o;
                }
            }
        }
    }
}

// ---------------------------------------------------------------------------
extern "C" void kernel_launch(void* const* d_in, const int* in_sizes, int n_in,
                              void* d_out, int out_size) {
    const float* NF  = (const float*)d_in[0];
    const int*   EIw = (const int*)d_in[1];
    const float* EA  = (const float*)d_in[2];
    const float* W1  = (const float*)d_in[3];
    const float* b1  = (const float*)d_in[4];
    const float* W2  = (const float*)d_in[5];
    const float* b2  = (const float*)d_in[6];
    float* out = (float*)d_out;

    static int attr_set = 0;
    if (!attr_set) {
        cudaFuncSetAttribute(k_pre, cudaFuncAttributeMaxDynamicSharedMemorySize, 131072);
        cudaFuncSetAttribute(k_edge, cudaFuncAttributeMaxDynamicSharedMemorySize, 73728);
        attr_set = 1;
    }

    k_detect<<<1, 32>>>(EIw);
    k_convw<<<(4 * 256 * 64 + 32768 + 255) / 256, 256>>>(W1, W2);
    k_pre<<<(N_NODES + 127) / 128, 256, 131072>>>(NF, b1);
    k_edge<<<(N_EDGES + 63) / 64, 256, 73728>>>(EIw, EA, b2, out);
}

// round 17
// speedup vs baseline: 1.6562x; 1.0489x over previous
#include <cuda_runtime.h>
#include <cuda_bf16.h>
#include <cuda_fp16.h>
#include <cstdint>

#define N_NODES 50000
#define N_EDGES 500000
#define D_NODE  128
#define D_EDGE  64
#define D_HID   256
#define D_OUT   64

// P[node][0:256] = nf@W1a + b1 ; P[node][256:512] = nf@W1b  (fp16, 51MB -> L2-resident)
__device__ __half g_P[(size_t)N_NODES * 512];
// W1^T bf16 split (panels 0-3 only, used by k_pre), swizzled 128B rows
__device__ __nv_bfloat16 gW1T_h[4 * 256 * 64];
__device__ __nv_bfloat16 gW1T_l[4 * 256 * 64];
// W1c^T fp16 [256 n][64 k] swizzled (edge GEMM1 B)
__device__ __half gW1cF[256 * 64];
// W2^T fp16, 4 k-panels of [64 n][64 k] swizzled (edge GEMM2 B)
__device__ __half gW2F[4 * 64 * 64];
__device__ int g_idx64;

// ---------------- helpers ----------------
__device__ __forceinline__ uint32_t s2u(const void* p) {
    return (uint32_t)__cvta_generic_to_shared(p);
}
__device__ __forceinline__ uint32_t pswz(uint32_t row, uint32_t kbyte) {
    return row * 128u + (kbyte ^ ((row & 7u) << 4));
}
__device__ __forceinline__ void ldm_x4(uint32_t* r, uint32_t addr) {
    asm volatile("ldmatrix.sync.aligned.m8n8.x4.shared.b16 {%0,%1,%2,%3}, [%4];"
        : "=r"(r[0]), "=r"(r[1]), "=r"(r[2]), "=r"(r[3]) : "r"(addr));
}
__device__ __forceinline__ void mma_bf(float* c, const uint32_t* a, const uint32_t* b) {
    asm volatile("mma.sync.aligned.m16n8k16.row.col.f32.bf16.bf16.f32 "
        "{%0,%1,%2,%3}, {%4,%5,%6,%7}, {%8,%9}, {%0,%1,%2,%3};"
        : "+f"(c[0]), "+f"(c[1]), "+f"(c[2]), "+f"(c[3])
        : "r"(a[0]), "r"(a[1]), "r"(a[2]), "r"(a[3]), "r"(b[0]), "r"(b[1]));
}
__device__ __forceinline__ void mma_fp(float* c, const uint32_t* a, const uint32_t* b) {
    asm volatile("mma.sync.aligned.m16n8k16.row.col.f32.f16.f16.f32 "
        "{%0,%1,%2,%3}, {%4,%5,%6,%7}, {%8,%9}, {%0,%1,%2,%3};"
        : "+f"(c[0]), "+f"(c[1]), "+f"(c[2]), "+f"(c[3])
        : "r"(a[0]), "r"(a[1]), "r"(a[2]), "r"(a[3]), "r"(b[0]), "r"(b[1]));
}
// bf16 2-way split (k_pre)
__device__ __forceinline__ void split2(float a, float b, uint32_t& hi, uint32_t& lo) {
    __nv_bfloat16 ha = __float2bfloat16_rn(a), hb = __float2bfloat16_rn(b);
    float la = a - __bfloat162float(ha), lb = b - __bfloat162float(hb);
    __nv_bfloat162 th; th.x = ha; th.y = hb;
    __nv_bfloat162 tl; tl.x = __float2bfloat16_rn(la); tl.y = __float2bfloat16_rn(lb);
    hi = *reinterpret_cast<uint32_t*>(&th);
    lo = *reinterpret_cast<uint32_t*>(&tl);
}
// fp16 pack
__device__ __forceinline__ uint32_t packh(float a, float b) {
    __half2 t = __halves2half2(__float2half_rn(a), __float2half_rn(b));
    return *reinterpret_cast<uint32_t*>(&t);
}
// load one fp16 P pair (cols c, c+1) as float2
__device__ __forceinline__ float2 ldP(const __half* p) {
    uint32_t u = __ldg(reinterpret_cast<const uint32_t*>(p));
    __half2 h = *reinterpret_cast<__half2*>(&u);
    return __half22float2(h);
}

// ---------------- dtype detect ----------------
__global__ void k_detect(const int* __restrict__ EIw) {
    if (threadIdx.x == 0 && blockIdx.x == 0) {
        int allzero = 1;
        #pragma unroll 1
        for (int i = 0; i < 64; i++)
            if (EIw[2 * i + 1] != 0) { allzero = 0; break; }
        g_idx64 = allzero;
    }
}

// ---------------- weight conversion ----------------
__global__ __launch_bounds__(256) void k_convw(
    const float* __restrict__ W1, const float* __restrict__ W2)
{
    int idx = blockIdx.x * 256 + threadIdx.x;
    if (idx < 4 * 256 * 64) {
        int p = idx / 16384, r = idx % 16384;
        int n = r / 64, kl = r % 64;
        float v = W1[(size_t)(p * 64 + kl) * D_HID + n];
        __nv_bfloat16 h = __float2bfloat16_rn(v);
        float lo = v - __bfloat162float(h);
        uint32_t off = (uint32_t)p * 32768u + pswz(n, 2 * kl);
        *(__nv_bfloat16*)((char*)gW1T_h + off) = h;
        *(__nv_bfloat16*)((char*)gW1T_l + off) = __float2bfloat16_rn(lo);
    } else if (idx < 4 * 256 * 64 + 16384) {
        int j = idx - 4 * 256 * 64;
        int n = j / 64, kl = j % 64;
        float v = W1[(size_t)(256 + kl) * D_HID + n];
        *(__half*)((char*)gW1cF + pswz(n, 2 * kl)) = __float2half_rn(v);
    } else if (idx < 4 * 256 * 64 + 32768) {
        int j = idx - 4 * 256 * 64 - 16384;
        int p = j / 4096, r = j % 4096;
        int n = r / 64, kl = r % 64;
        float v = W2[(size_t)(p * 64 + kl) * D_OUT + n];
        *(__half*)((char*)gW2F + (uint32_t)p * 8192u + pswz(n, 2 * kl)) = __float2half_rn(v);
    }
}

// ---------------- kernel 1: P table via bf16-split MMA, fp16 store --------
__global__ __launch_bounds__(256) void k_pre(
    const float* __restrict__ NF, const float* __restrict__ b1)
{
    extern __shared__ char sm[];
    const uint32_t uA_h = s2u(sm), uA_l = uA_h + 32768;
    const uint32_t uB_h = uA_h + 65536, uB_l = uA_h + 98304;

    const int tid = threadIdx.x, lane = tid & 31, wid = tid >> 5;
    const int wm = wid & 3, wn = wid >> 2;
    const int m0 = blockIdx.x * 128;

    const uint32_t a_row = (lane & 7) + ((lane >> 3) & 1) * 8;
    const uint32_t a_kb  = (lane >> 4) * 16;
    const uint32_t b_row = (lane & 7) + (lane >> 4) * 8;
    const uint32_t b_kb  = ((lane >> 3) & 1) * 16;

    #pragma unroll
    for (int t = 0; t < 32; t++) {
        int idx = tid + t * 256;
        int e = idx >> 6, kp = idx & 63;
        int gm = m0 + e;
        float2 v = make_float2(0.f, 0.f);
        if (gm < N_NODES) v = *(const float2*)(NF + (size_t)gm * D_NODE + 2 * kp);
        uint32_t hi, lo; split2(v.x, v.y, hi, lo);
        uint32_t off = (uint32_t)(kp >> 5) * 16384u + pswz(e, (kp & 31) * 4);
        *(uint32_t*)(sm + off) = hi;
        *(uint32_t*)(sm + 32768 + off) = lo;
    }
    __syncthreads();

    for (int c = 0; c < 4; c++) {
        const int p0 = (c < 2) ? 0 : 2;
        const int wc0 = (c & 1) * 128;
        const uint32_t* srcH = (const uint32_t*)(gW1T_h);
        const uint32_t* srcL = (const uint32_t*)(gW1T_l);
        #pragma unroll
        for (int d = 0; d < 2; d++) {
            size_t so = ((size_t)(p0 + d) * 16384 + (size_t)wc0 * 64) / 2;
            #pragma unroll
            for (int t = 0; t < 16; t++) {
                int w = tid + t * 256;
                ((uint32_t*)(sm + 65536 + d * 16384))[w] = srcH[so + w];
                ((uint32_t*)(sm + 98304 + d * 16384))[w] = srcL[so + w];
            }
        }
        __syncthreads();

        float acc[2][8][4];
        #pragma unroll
        for (int i = 0; i < 2; i++)
            #pragma unroll
            for (int j = 0; j < 8; j++)
                #pragma unroll
                for (int r = 0; r < 4; r++) acc[i][j][r] = 0.f;

        #pragma unroll
        for (int ks = 0; ks < 8; ks++) {
            const uint32_t pan = (uint32_t)(ks >> 2) * 16384u;
            const uint32_t kb = (ks & 3) * 32;
            uint32_t Ah[2][4], Al[2][4], Bh[4][4], Bl[4][4];
            #pragma unroll
            for (int mt = 0; mt < 2; mt++) {
                uint32_t row = wm * 32 + mt * 16 + a_row;
                uint32_t off = pan + pswz(row, kb + a_kb);
                ldm_x4(Ah[mt], uA_h + off);
                ldm_x4(Al[mt], uA_l + off);
            }
            #pragma unroll
            for (int np = 0; np < 4; np++) {
                uint32_t row = wn * 64 + np * 16 + b_row;
                uint32_t off = pan + pswz(row, kb + b_kb);
                ldm_x4(Bh[np], uB_h + off);
                ldm_x4(Bl[np], uB_l + off);
            }
            #pragma unroll
            for (int mt = 0; mt < 2; mt++)
                #pragma unroll
                for (int nt = 0; nt < 8; nt++) {
                    const uint32_t* bh = &Bh[nt >> 1][(nt & 1) * 2];
                    const uint32_t* bl = &Bl[nt >> 1][(nt & 1) * 2];
                    mma_bf(acc[mt][nt], Ah[mt], bh);
                    mma_bf(acc[mt][nt], Ah[mt], bl);
                    mma_bf(acc[mt][nt], Al[mt], bh);
                }
        }

        const int g = lane >> 2, tg2 = (lane & 3) * 2;
        #pragma unroll
        for (int mt = 0; mt < 2; mt++) {
            #pragma unroll
            for (int rr = 0; rr < 2; rr++) {
                int gm = m0 + wm * 32 + mt * 16 + g + rr * 8;
                if (gm < N_NODES) {
                    #pragma unroll
                    for (int nt = 0; nt < 8; nt++) {
                        int col = c * 128 + wn * 64 + nt * 8 + tg2;
                        float ox = acc[mt][nt][rr * 2 + 0];
                        float oy = acc[mt][nt][rr * 2 + 1];
                        if (c < 2) { ox += b1[col]; oy += b1[col + 1]; }
                        *(uint32_t*)(g_P + (size_t)gm * 512 + col) = packh(ox, oy);
                    }
                }
            }
        }
        __syncthreads();
    }
}

// ---------------- kernel 2: pure-fp16 register-chained edge MLP -----------
// 64 edges/CTA, 256 threads (8 warps: wm4 x wn2), 72KB smem, 2 CTAs/SM.
// fp16 P table (L2-resident, half gather bytes).
__global__ __launch_bounds__(256, 2) void k_edge(
    const int* __restrict__ EIw, const float* __restrict__ EA,
    const float* __restrict__ b2, float* __restrict__ out)
{
    extern __shared__ char sm[];
    const uint32_t uBase = s2u(sm);
    const uint32_t uEA = uBase;                  // 8KB fp16 EA
    const uint32_t uW1 = uBase + 8192;           // 32KB fp16 W1c
    const uint32_t uW2 = uBase + 40960;          // 32KB fp16 W2
    float* red = (float*)sm;   // overlays EA/W1c after final sync

    __shared__ int sRow[64], sCol[64];

    const int tid = threadIdx.x, lane = tid & 31, wid = tid >> 5;
    const int wm = wid >> 1, wn = wid & 1;   // 4 x 2 warp grid
    const int e0 = blockIdx.x * 64;
    const int g = lane >> 2, tg2 = (lane & 3) * 2;

    const uint32_t a_row = (lane & 7) + ((lane >> 3) & 1) * 8;
    const uint32_t a_kb  = (lane >> 4) * 16;
    const uint32_t b_row = (lane & 7) + (lane >> 4) * 8;
    const uint32_t b_kb  = ((lane >> 3) & 1) * 16;

    if (tid < 64) {
        int e = e0 + tid;
        int r = 0, c = 0;
        if (e < N_EDGES) {
            if (g_idx64) { r = EIw[(size_t)2 * e]; c = EIw[(size_t)2 * (N_EDGES + e)]; }
            else         { r = EIw[e];             c = EIw[(size_t)N_EDGES + e]; }
        }
        sRow[tid] = min(max(r, 0), N_NODES - 1);
        sCol[tid] = min(max(c, 0), N_NODES - 1);
    }
    // EA tile [64e][64k] -> single fp16 panel
    #pragma unroll
    for (int t = 0; t < 8; t++) {
        int idx = tid + t * 256;
        int e = idx >> 5, kp = idx & 31;
        int ge = e0 + e;
        float2 v = make_float2(0.f, 0.f);
        if (ge < N_EDGES) v = *(const float2*)(EA + (size_t)ge * D_EDGE + 2 * kp);
        *(uint32_t*)(sm + pswz(e, kp * 4)) = packh(v.x, v.y);
    }
    // W1c fp16 [256n][64k]: 8192 words
    #pragma unroll
    for (int t = 0; t < 32; t++) {
        int w = tid + t * 256;
        ((uint32_t*)(sm + 8192))[w] = ((const uint32_t*)gW1cF)[w];
    }
    // W2 fp16 4 k-panels: 8192 words
    #pragma unroll
    for (int t = 0; t < 32; t++) {
        int w = tid + t * 256;
        ((uint32_t*)(sm + 40960))[w] = ((const uint32_t*)gW2F)[w];
    }
    __syncthreads();   // the ONLY barrier before the output reduction

    float d[8][4];
    #pragma unroll
    for (int j = 0; j < 8; j++)
        #pragma unroll
        for (int r = 0; r < 4; r++) d[j][r] = 0.f;

    const int eg = wm * 16 + g;

    #pragma unroll 1
    for (int h = 0; h < 2; h++) {
        // ---- GEMM1: acc[16e x 64hid], hid slice = h*128 + wn*64 ----
        float acc[8][4];
        #pragma unroll
        for (int j = 0; j < 8; j++)
            #pragma unroll
            for (int r = 0; r < 4; r++) acc[j][r] = 0.f;

        #pragma unroll
        for (int ks = 0; ks < 4; ks++) {
            const uint32_t kb = ks * 32;
            uint32_t Ah[4];
            ldm_x4(Ah, uEA + pswz(wm * 16 + a_row, kb + a_kb));
            #pragma unroll
            for (int np = 0; np < 4; np++) {
                uint32_t B4[4];
                uint32_t row = h * 128 + wn * 64 + np * 16 + b_row;
                ldm_x4(B4, uW1 + pswz(row, kb + b_kb));
                #pragma unroll
                for (int pr = 0; pr < 2; pr++)
                    mma_fp(acc[np * 2 + pr], Ah, &B4[pr * 2]);
            }
        }

        // ---- epilogue (gather fp16 P, relu, fp16 pack) + GEMM2 partial ----
        const int pc = h * 128 + wn * 64;
        const __half* paG  = g_P + (size_t)sRow[eg]     * 512 + pc;
        const __half* paG8 = g_P + (size_t)sRow[eg + 8] * 512 + pc;
        const __half* pbG  = g_P + (size_t)sCol[eg]     * 512 + 256 + pc;
        const __half* pbG8 = g_P + (size_t)sCol[eg + 8] * 512 + 256 + pc;
        const uint32_t w2 = uW2 + (uint32_t)(2 * h + wn) * 8192u;

        #pragma unroll
        for (int j = 0; j < 4; j++) {
            const int c0 = j * 16 + tg2, c1 = c0 + 8;
            float2 va0 = ldP(paG  + c0);
            float2 vb0 = ldP(pbG  + c0);
            float2 wa0 = ldP(paG8 + c0);
            float2 wb0 = ldP(pbG8 + c0);
            float2 va1 = ldP(paG  + c1);
            float2 vb1 = ldP(pbG  + c1);
            float2 wa1 = ldP(paG8 + c1);
            float2 wb1 = ldP(pbG8 + c1);

            float x00 = fmaxf(acc[2*j][0]   + va0.x + vb0.x, 0.f);
            float x01 = fmaxf(acc[2*j][1]   + va0.y + vb0.y, 0.f);
            float x10 = fmaxf(acc[2*j][2]   + wa0.x + wb0.x, 0.f);
            float x11 = fmaxf(acc[2*j][3]   + wa0.y + wb0.y, 0.f);
            float y00 = fmaxf(acc[2*j+1][0] + va1.x + vb1.x, 0.f);
            float y01 = fmaxf(acc[2*j+1][1] + va1.y + vb1.y, 0.f);
            float y10 = fmaxf(acc[2*j+1][2] + wa1.x + wb1.x, 0.f);
            float y11 = fmaxf(acc[2*j+1][3] + wa1.y + wb1.y, 0.f);

            // C-tile pair -> A-fragment (m16k16), single fp16
            uint32_t aH[4];
            aH[0] = packh(x00, x01);
            aH[1] = packh(x10, x11);
            aH[2] = packh(y00, y01);
            aH[3] = packh(y10, y11);

            #pragma unroll
            for (int np = 0; np < 4; np++) {
                uint32_t B4[4];
                ldm_x4(B4, w2 + pswz(np * 16 + b_row, j * 32 + b_kb));
                #pragma unroll
                for (int pr = 0; pr < 2; pr++)
                    mma_fp(d[np * 2 + pr], aH, &B4[pr * 2]);
            }
        }
    }

    // ---- cross-wn reduction (stride-68 buffer overlaying EA/W1c) ----
    __syncthreads();
    if (wn == 1) {
        #pragma unroll
        for (int nt = 0; nt < 8; nt++) {
            int n = nt * 8 + tg2;
            int el = wm * 16 + g;
            *(float2*)(red + (size_t)el * 68 + n) =
                make_float2(d[nt][0], d[nt][1]);
            *(float2*)(red + (size_t)(el + 8) * 68 + n) =
                make_float2(d[nt][2], d[nt][3]);
        }
    }
    __syncthreads();
    if (wn == 0) {
        #pragma unroll
        for (int rr = 0; rr < 2; rr++) {
            int el = wm * 16 + g + rr * 8;
            int ge = e0 + el;
            if (ge < N_EDGES) {
                #pragma unroll
                for (int nt = 0; nt < 8; nt++) {
                    int n = nt * 8 + tg2;
                    float2 r2 = *(float2*)(red + (size_t)el * 68 + n);
                    float2 bb = *(const float2*)(b2 + n);
                    float2 o;
                    o.x = d[nt][rr * 2 + 0] + r2.x + bb.x;
                    o.y = d[nt][rr * 2 + 1] + r2.y + bb.y;
                    *(float2*)(out + (size_t)ge * D_OUT + n) = o;
                }
            }
        }
    }
}

// ---------------------------------------------------------------------------
extern "C" void kernel_launch(void* const* d_in, const int* in_sizes, int n_in,
                              void* d_out, int out_size) {
    const float* NF  = (const float*)d_in[0];
    const int*   EIw = (const int*)d_in[1];
    const float* EA  = (const float*)d_in[2];
    const float* W1  = (const float*)d_in[3];
    const float* b1  = (const float*)d_in[4];
    const float* W2  = (const float*)d_in[5];
    const float* b2  = (const float*)d_in[6];
    float* out = (float*)d_out;

    static int attr_set = 0;
    if (!attr_set) {
        cudaFuncSetAttribute(k_pre, cudaFuncAttributeMaxDynamicSharedMemorySize, 131072);
        cudaFuncSetAttribute(k_edge, cudaFuncAttributeMaxDynamicSharedMemorySize, 73728);
        attr_set = 1;
    }

    k_detect<<<1, 32>>>(EIw);
    k_convw<<<(4 * 256 * 64 + 32768 + 255) / 256, 256>>>(W1, W2);
    k_pre<<<(N_NODES + 127) / 128, 256, 131072>>>(NF, b1);
    k_edge<<<(N_EDGES + 63) / 64, 256, 73728>>>(EIw, EA, b2, out);
}